// round 7
// baseline (speedup 1.0000x reference)
#include <cuda_runtime.h>
#include <cstdint>

// Depthwise Conv1d, K=3, pad=1, stride=1.
// inputs: [B=32, C=128, L=8192] f32, weight: [128,3] f32, bias: [128] f32
// out[b,c,l] = w0*x[l-1] + w1*x[l] + w2*x[l+1] + bias  (x zero-padded)
//
// 32 elems/thread (8x float4), all loads front-batched (MLP_p1=8).
// 256 groups/row, 32 groups/warp -> warps row-aligned: halos via shuffle,
// weights warp-uniform. Grid = 4096 CTAs (halves wave count vs 16/thread).

#define C_CH   128
#define L_LEN  8192
#define EPT    32                                   // elems per thread
#define GROUPS_PER_ROW   (L_LEN / EPT)              // 256
#define TOTAL_ROWS       (32 * C_CH)                // 4096

__global__ __launch_bounds__(256)
void dwconv1d_kernel(const float* __restrict__ x,
                     const float* __restrict__ w,
                     const float* __restrict__ b,
                     float* __restrict__ y) {
    const int t    = blockIdx.x * blockDim.x + threadIdx.x;  // group index
    const int lane = threadIdx.x & 31;
    const int row  = t >> 8;                 // /256 -> (b*C + c), warp-uniform
    const int pos  = (t & 255) << 5;         // start element within row
    const int c    = row & (C_CH - 1);       // warp-uniform channel

    const float* __restrict__ xr = x + (size_t)row * L_LEN;
    float*       __restrict__ yr = y + (size_t)row * L_LEN;

    // Front-batched payload: 8 x LDG.128
    float4 v[8];
#pragma unroll
    for (int i = 0; i < 8; i++)
        v[i] = *reinterpret_cast<const float4*>(xr + pos + 4 * i);

    // Warp-edge halos: only lane 0 / lane 31 touch memory.
    float xl_edge = 0.0f, xh_edge = 0.0f;
    if (lane == 0 && pos != 0)
        xl_edge = xr[pos - 1];
    if (lane == 31 && pos != L_LEN - EPT)
        xh_edge = xr[pos + EPT];

    // Interior halos via shuffle: lane i-1's last elem / lane i+1's first elem.
    float xl = __shfl_up_sync(0xffffffffu, v[7].w, 1);
    float xh = __shfl_down_sync(0xffffffffu, v[0].x, 1);
    if (lane == 0)  xl = xl_edge;
    if (lane == 31) xh = xh_edge;

    // Warp-uniform coefficients.
    const float w0 = w[3 * c + 0];
    const float w1 = w[3 * c + 1];
    const float w2 = w[3 * c + 2];
    const float bb = b[c];

    // Compute in place with a running "previous element" so outputs reuse
    // the input registers (keeps register count low for occupancy).
    float prev = xl;                      // element at index -1
#pragma unroll
    for (int i = 0; i < 8; i++) {
        const float nxt = (i < 7) ? v[i + 1].x : xh;   // element after v[i].w
        const float e0 = v[i].x, e1 = v[i].y, e2 = v[i].z, e3 = v[i].w;
        float4 o;
        o.x = fmaf(w0, prev, fmaf(w1, e0, fmaf(w2, e1, bb)));
        o.y = fmaf(w0, e0,   fmaf(w1, e1, fmaf(w2, e2, bb)));
        o.z = fmaf(w0, e1,   fmaf(w1, e2, fmaf(w2, e3, bb)));
        o.w = fmaf(w0, e2,   fmaf(w1, e3, fmaf(w2, nxt, bb)));
        prev = e3;
        v[i] = o;                          // overwrite input reg with output
    }

    // Batched stores: 8 x STG.128
    float4* yv = reinterpret_cast<float4*>(yr + pos);
#pragma unroll
    for (int i = 0; i < 8; i++)
        yv[i] = v[i];
}

extern "C" void kernel_launch(void* const* d_in, const int* in_sizes, int n_in,
                              void* d_out, int out_size) {
    const float* x = (const float*)d_in[0];   // inputs [32,128,8192]
    const float* w = (const float*)d_in[1];   // weight [128,3]
    const float* b = (const float*)d_in[2];   // bias   [128]
    float* y = (float*)d_out;

    const int total_groups = TOTAL_ROWS * GROUPS_PER_ROW;    // 1,048,576
    dwconv1d_kernel<<<total_groups / 256, 256>>>(x, w, b, y);
}

// round 11
// speedup vs baseline: 1.7268x; 1.7268x over previous
#include <cuda_runtime.h>
#include <cstdint>

// Depthwise Conv1d, K=3, pad=1, stride=1.
// inputs: [B=32, C=128, L=8192] f32, weight: [128,3] f32, bias: [128] f32
// out[b,c,l] = w0*x[l-1] + w1*x[l] + w2*x[l+1] + bias  (x zero-padded)
//
// Coalesced layout: each WARP owns a contiguous 512-elem tile of one row,
// as 4 chunks of 128 elems. In chunk j, lane i holds float4 at j*128 + 4i,
// so each warp-wide LDG.128/STG.128 covers exactly 512 contiguous bytes
// (4 cache lines = minimum L1 wavefronts). Lane coverage is exact:
// lane31.v[j].w = elem j*128+127, lane0.v[j+1].x = elem (j+1)*128.
// Halos: intra-chunk shfl +/-1; cross-chunk register broadcast; tile edges
// via 2 predicated scalar loads per warp.

#define C_CH       128
#define L_LEN      8192
#define WARP_TILE  512                        // elems per warp (4 chunks x 128)
#define TILES_PER_ROW (L_LEN / WARP_TILE)     // 16
#define TOTAL_ROWS (32 * C_CH)                // 4096

__global__ __launch_bounds__(256)
void dwconv1d_kernel(const float* __restrict__ x,
                     const float* __restrict__ w,
                     const float* __restrict__ b,
                     float* __restrict__ y) {
    const int gtid   = blockIdx.x * blockDim.x + threadIdx.x;
    const int lane   = threadIdx.x & 31;
    const int warpId = gtid >> 5;
    const int row    = warpId >> 4;            // /16 -> (b*C + c), warp-uniform
    const int tile   = warpId & 15;            // warp tile within row
    const int base   = tile * WARP_TILE;       // tile start elem, warp-uniform
    const int c      = row & (C_CH - 1);

    const float* __restrict__ xr = x + (size_t)row * L_LEN + base;
    float*       __restrict__ yr = y + (size_t)row * L_LEN + base;
    const int lo = lane * 4;                   // lane offset within a chunk

    // Front-batched coalesced loads: 4 x LDG.128, each warp-wide = 512 B.
    float4 v[4];
#pragma unroll
    for (int j = 0; j < 4; j++)
        v[j] = *reinterpret_cast<const float4*>(xr + j * 128 + lo);

    // Warp-tile edge halos (1 active lane each; L2/L1 hits).
    float xl_edge = 0.0f, xh_edge = 0.0f;
    if (lane == 0 && base != 0)
        xl_edge = xr[-1];
    if (lane == 31 && base != L_LEN - WARP_TILE)
        xh_edge = xr[WARP_TILE];

    // Intra-chunk halos via shfl.
    float xl[4], xh[4];
#pragma unroll
    for (int j = 0; j < 4; j++) {
        xl[j] = __shfl_up_sync(0xffffffffu, v[j].w, 1);     // lane i-1's last
        xh[j] = __shfl_down_sync(0xffffffffu, v[j].x, 1);   // lane i+1's first
    }
    // Cross-chunk: lane0 of chunk j needs lane31's v[j-1].w;
    //             lane31 of chunk j needs lane0's v[j+1].x.
    const float c0_last  = __shfl_sync(0xffffffffu, v[0].w, 31);
    const float c1_last  = __shfl_sync(0xffffffffu, v[1].w, 31);
    const float c2_last  = __shfl_sync(0xffffffffu, v[2].w, 31);
    const float c1_first = __shfl_sync(0xffffffffu, v[1].x, 0);
    const float c2_first = __shfl_sync(0xffffffffu, v[2].x, 0);
    const float c3_first = __shfl_sync(0xffffffffu, v[3].x, 0);
    if (lane == 0) {
        xl[0] = xl_edge; xl[1] = c0_last; xl[2] = c1_last; xl[3] = c2_last;
    }
    if (lane == 31) {
        xh[0] = c1_first; xh[1] = c2_first; xh[2] = c3_first; xh[3] = xh_edge;
    }

    // Warp-uniform coefficients.
    const float w0 = w[3 * c + 0];
    const float w1 = w[3 * c + 1];
    const float w2 = w[3 * c + 2];
    const float bb = b[c];

    // Compute, overwriting input registers with outputs.
#pragma unroll
    for (int j = 0; j < 4; j++) {
        const float e0 = v[j].x, e1 = v[j].y, e2 = v[j].z, e3 = v[j].w;
        float4 o;
        o.x = fmaf(w0, xl[j], fmaf(w1, e0, fmaf(w2, e1, bb)));
        o.y = fmaf(w0, e0,    fmaf(w1, e1, fmaf(w2, e2, bb)));
        o.z = fmaf(w0, e1,    fmaf(w1, e2, fmaf(w2, e3, bb)));
        o.w = fmaf(w0, e2,    fmaf(w1, e3, fmaf(w2, xh[j], bb)));
        v[j] = o;
    }

    // Coalesced stores: 4 x STG.128, each warp-wide = 512 B.
#pragma unroll
    for (int j = 0; j < 4; j++)
        *reinterpret_cast<float4*>(yr + j * 128 + lo) = v[j];
}

extern "C" void kernel_launch(void* const* d_in, const int* in_sizes, int n_in,
                              void* d_out, int out_size) {
    const float* x = (const float*)d_in[0];   // inputs [32,128,8192]
    const float* w = (const float*)d_in[1];   // weight [128,3]
    const float* b = (const float*)d_in[2];   // bias   [128]
    float* y = (float*)d_out;

    const int total_warps   = TOTAL_ROWS * TILES_PER_ROW;    // 65536
    const int total_threads = total_warps * 32;              // 2,097,152
    dwconv1d_kernel<<<total_threads / 256, 256>>>(x, w, b, y);
}